// round 6
// baseline (speedup 1.0000x reference)
#include <cuda_runtime.h>
#include <math_constants.h>

#define N_NODES 50000
#define N_EDGES 600000
#define REL_NUM 500
#define E_HID 128

// ---------------- device scratch (no allocation allowed) ----------------
__device__ float    g_remb[REL_NUM * E_HID];   // ww(rel_emb): 256 KB
__device__ float    g_dp[N_EDGES];             // per-edge logits: 2.4 MB
__device__ unsigned g_max_u;                   // ordered-uint encoding of max
__device__ float    g_sumexp;

// monotonic float <-> uint mapping (preserves ordering incl. negatives)
__device__ __forceinline__ unsigned f2u_ord(float f) {
    unsigned u = __float_as_uint(f);
    return (u & 0x80000000u) ? ~u : (u | 0x80000000u);
}
__device__ __forceinline__ float u2f_ord(unsigned u) {
    unsigned b = (u & 0x80000000u) ? (u & 0x7FFFFFFFu) : ~u;
    return __uint_as_float(b);
}

// ---------------- kernels ----------------

__global__ void k_init() {
    g_max_u  = 0u;       // maps below every real float
    g_sumexp = 0.0f;
}

// r_emb = rel_emb @ ww_w^T  (into g_remb), rel_out = rel_emb @ rel_w^T (into out)
// one block per relation row, 128 threads (one per output column)
__global__ void k_relgemm(const float* __restrict__ rel_emb,
                          const float* __restrict__ ww_w,
                          const float* __restrict__ rel_w,
                          float* __restrict__ rel_out) {
    __shared__ float row[E_HID];
    int r = blockIdx.x;
    int t = threadIdx.x;
    row[t] = rel_emb[r * E_HID + t];
    __syncthreads();
    const float* w1 = ww_w + t * E_HID;   // [out,in] layout; output col t
    const float* w2 = rel_w + t * E_HID;
    float s1 = 0.f, s2 = 0.f;
#pragma unroll 8
    for (int k = 0; k < E_HID; ++k) {
        float rv = row[k];
        s1 = fmaf(rv, w1[k], s1);
        s2 = fmaf(rv, w2[k], s2);
    }
    g_remb[r * E_HID + t]  = s1;
    rel_out[r * E_HID + t] = s2;
}

// per-edge logit: dp[e] = dot(x[src]+r_emb[etype], x[dst]); track global max
__global__ void k_edgedot(const float4* __restrict__ x4,
                          const int* __restrict__ eidx,
                          const int* __restrict__ etype) {
    const float4* remb4 = (const float4*)g_remb;
    int lane   = threadIdx.x & 31;
    int warp   = (blockIdx.x * blockDim.x + threadIdx.x) >> 5;
    int nwarps = (gridDim.x * blockDim.x) >> 5;

    float lmax = -CUDART_INF_F;
    for (int e = warp; e < N_EDGES; e += nwarps) {
        int s = eidx[e];
        int d = eidx[N_EDGES + e];
        int t = etype[e];
        float4 xs = x4[(long long)s * 32 + lane];
        float4 xd = x4[(long long)d * 32 + lane];
        float4 re = remb4[t * 32 + lane];
        float v = (xs.x + re.x) * xd.x;
        v = fmaf(xs.y + re.y, xd.y, v);
        v = fmaf(xs.z + re.z, xd.z, v);
        v = fmaf(xs.w + re.w, xd.w, v);
#pragma unroll
        for (int o = 16; o; o >>= 1) v += __shfl_xor_sync(0xffffffffu, v, o);
        if (lane == 0) g_dp[e] = v;
        lmax = fmaxf(lmax, v);   // all lanes hold full dot after reduce
    }
    // hierarchical max: warp(lane0) -> shared -> one global atomic per block
    __shared__ unsigned smax;
    if (threadIdx.x == 0) smax = 0u;
    __syncthreads();
    if (lane == 0) atomicMax(&smax, f2u_ord(lmax));
    __syncthreads();
    if (threadIdx.x == 0) atomicMax(&g_max_u, smax);
}

// sum of exp(dp - max), hierarchical reduction, one atomicAdd per block
__global__ void k_sumexp() {
    float mx = u2f_ord(g_max_u);
    float s = 0.f;
    for (int i = blockIdx.x * blockDim.x + threadIdx.x; i < N_EDGES;
         i += gridDim.x * blockDim.x)
        s += __expf(g_dp[i] - mx);
#pragma unroll
    for (int o = 16; o; o >>= 1) s += __shfl_xor_sync(0xffffffffu, s, o);
    __shared__ float ssum[32];
    int lane = threadIdx.x & 31, wid = threadIdx.x >> 5;
    if (lane == 0) ssum[wid] = s;
    __syncthreads();
    if (threadIdx.x == 0) {
        float t = 0.f;
        int nw = blockDim.x >> 5;
        for (int i = 0; i < nw; ++i) t += ssum[i];
        atomicAdd(&g_sumexp, t);
    }
}

// scatter: out[dst] += attn[e] * (x[src] + r_emb[etype]) via vector red.v4.f32
__global__ void k_scatter(const float4* __restrict__ x4,
                          const int* __restrict__ eidx,
                          const int* __restrict__ etype,
                          float* __restrict__ out) {
    const float4* remb4 = (const float4*)g_remb;
    float mx  = u2f_ord(g_max_u);
    float inv = 1.0f / g_sumexp;
    int lane   = threadIdx.x & 31;
    int warp   = (blockIdx.x * blockDim.x + threadIdx.x) >> 5;
    int nwarps = (gridDim.x * blockDim.x) >> 5;

    for (int e = warp; e < N_EDGES; e += nwarps) {
        int s = eidx[e];
        int d = eidx[N_EDGES + e];
        int t = etype[e];
        float a = __expf(g_dp[e] - mx) * inv;
        float4 xs = x4[(long long)s * 32 + lane];
        float4 re = remb4[t * 32 + lane];
        float wx = (xs.x + re.x) * a;
        float wy = (xs.y + re.y) * a;
        float wz = (xs.z + re.z) * a;
        float ww = (xs.w + re.w) * a;
        float* p = out + (long long)d * E_HID + lane * 4;
        asm volatile("red.global.add.v4.f32 [%0], {%1, %2, %3, %4};"
                     :: "l"(p), "f"(wx), "f"(wy), "f"(wz), "f"(ww)
                     : "memory");
    }
}

// relu on x_e region + res_att passthrough in one pass
__global__ void k_finalize(const float* __restrict__ res_att,
                           float* __restrict__ out) {
    const int XE = N_NODES * E_HID;                 // 6,400,000
    const int RES_OFF = XE + REL_NUM * E_HID;       // 6,464,000
    int total = XE + N_EDGES;                       // 7,000,000 work items
    for (int i = blockIdx.x * blockDim.x + threadIdx.x; i < total;
         i += gridDim.x * blockDim.x) {
        if (i < XE) {
            out[i] = fmaxf(out[i], 0.0f);
        } else {
            int j = i - XE;
            out[RES_OFF + j] = res_att[j];
        }
    }
}

// ---------------- launch ----------------
extern "C" void kernel_launch(void* const* d_in, const int* in_sizes, int n_in,
                              void* d_out, int out_size) {
    const float* x       = (const float*)d_in[0];
    const int*   eidx    = (const int*)d_in[1];
    const int*   etype   = (const int*)d_in[2];
    const float* rel_emb = (const float*)d_in[3];
    const float* res_att = (const float*)d_in[4];
    const float* ww_w    = (const float*)d_in[5];
    const float* rel_w   = (const float*)d_in[6];
    float* out = (float*)d_out;

    // zero the x_e accumulation region (output poisoned with 0xAA)
    cudaMemsetAsync(out, 0, (size_t)N_NODES * E_HID * sizeof(float), 0);

    k_init<<<1, 1>>>();
    k_relgemm<<<REL_NUM, E_HID>>>(rel_emb, ww_w, rel_w, out + N_NODES * E_HID);

    const float4* x4 = (const float4*)x;
    k_edgedot<<<2368, 256>>>(x4, eidx, etype);
    k_sumexp<<<1184, 256>>>();
    k_scatter<<<2368, 256>>>(x4, eidx, etype, out);
    k_finalize<<<2048, 256>>>(res_att, out);
}